// round 2
// baseline (speedup 1.0000x reference)
#include <cuda_runtime.h>

#define B_DIM 4096
#define K_DIM 64
#define D_DIM 512
#define POOL_N 1000000
#define THREADS 512

// smem layout: rows[K][D] | x[D] | wact[K]
#define SMEM_FLOATS (K_DIM * D_DIM + D_DIM + K_DIM)
#define SMEM_BYTES (SMEM_FLOATS * sizeof(float))

__global__ void __launch_bounds__(THREADS, 1)
sparse_exec_kernel(const float* __restrict__ x,
                   const int* __restrict__ indices,
                   const float* __restrict__ weights,
                   const float* __restrict__ pool,
                   float* __restrict__ out) {
    extern __shared__ float smem[];
    float* s_rows = smem;                    // K*D
    float* s_x    = smem + K_DIM * D_DIM;    // D
    float* s_wact = s_x + D_DIM;             // K

    const int b    = blockIdx.x;
    const int tid  = threadIdx.x;
    const int warp = tid >> 5;
    const int lane = tid & 31;

    // Load x[b] into shared (one float per thread, coalesced 2KB)
    s_x[tid] = x[(size_t)b * D_DIM + tid];
    __syncthreads();

    // ---- Phase 1: each warp gathers 4 pool rows, caches to smem, computes dots ----
    // Preload indices up-front to break address dependency and maximize MLP.
    int idxs[4];
#pragma unroll
    for (int r = 0; r < 4; r++) {
        int k = warp * 4 + r;
        int v = indices[(size_t)b * K_DIM + k];
        // defensive clamp (1 instr; protects against any OOB)
        v = v < 0 ? 0 : (v >= POOL_N ? POOL_N - 1 : v);
        idxs[r] = v;
    }

    const float4* sx4 = (const float4*)s_x;

#pragma unroll
    for (int r = 0; r < 4; r++) {
        int k = warp * 4 + r;
        const float4* prow = (const float4*)(pool + (size_t)idxs[r] * D_DIM);
        float4* srow = (float4*)(s_rows + k * D_DIM);
        float dot = 0.0f;
#pragma unroll
        for (int i = 0; i < 4; i++) {
            int j = i * 32 + lane;           // float4 index within row (0..127)
            float4 v = __ldg(&prow[j]);      // coalesced 512B per instruction
            srow[j] = v;                     // cache for phase 2
            float4 xv = sx4[j];
            dot += v.x * xv.x + v.y * xv.y + v.z * xv.z + v.w * xv.w;
        }
        // warp reduction
#pragma unroll
        for (int off = 16; off; off >>= 1)
            dot += __shfl_xor_sync(0xffffffffu, dot, off);
        if (lane == 0)
            s_wact[k] = tanhf(dot) * weights[(size_t)b * K_DIM + k];
    }
    __syncthreads();

    // ---- Phase 2: out[b][d] = x[d] + sum_k wact[k] * rows[k][d] ----
    float acc = s_x[tid];
#pragma unroll 8
    for (int k = 0; k < K_DIM; k++)
        acc = fmaf(s_wact[k], s_rows[k * D_DIM + tid], acc);

    out[(size_t)b * D_DIM + tid] = acc;
}

extern "C" void kernel_launch(void* const* d_in, const int* in_sizes, int n_in,
                              void* d_out, int out_size) {
    const float* x       = (const float*)d_in[0];
    const int*   indices = (const int*)d_in[1];
    const float* weights = (const float*)d_in[2];
    const float* pool    = (const float*)d_in[3];
    float*       out     = (float*)d_out;

    cudaFuncSetAttribute(sparse_exec_kernel,
                         cudaFuncAttributeMaxDynamicSharedMemorySize, SMEM_BYTES);

    sparse_exec_kernel<<<B_DIM, THREADS, SMEM_BYTES>>>(x, indices, weights, pool, out);
}

// round 3
// speedup vs baseline: 1.1346x; 1.1346x over previous
#include <cuda_runtime.h>

#define B_DIM 4096
#define K_DIM 64
#define D_DIM 512
#define POOL_N 1000000
#define THREADS 512
#define SPLIT 2
#define K_PER (K_DIM / SPLIT)          // 32 rows per CTA
#define ROWS_PER_WARP (K_PER / 16)     // 2 rows per warp

// smem layout: rows[K_PER][D] | x[D] | wact[K_PER]
#define SMEM_FLOATS (K_PER * D_DIM + D_DIM + K_PER)
#define SMEM_BYTES (SMEM_FLOATS * sizeof(float))

// 8MB scratch for split-1 partials (static __device__ allocation is allowed)
__device__ float g_scratch[(size_t)B_DIM * D_DIM];

__global__ void __launch_bounds__(THREADS, 2)
sparse_gather_kernel(const float* __restrict__ x,
                     const int* __restrict__ indices,
                     const float* __restrict__ weights,
                     const float* __restrict__ pool,
                     float* __restrict__ out) {
    extern __shared__ float smem[];
    float* s_rows = smem;                      // K_PER * D
    float* s_x    = smem + K_PER * D_DIM;      // D
    float* s_wact = s_x + D_DIM;               // K_PER

    const int b     = blockIdx.x >> 1;         // batch row
    const int split = blockIdx.x & 1;          // 0 or 1
    const int tid   = threadIdx.x;
    const int warp  = tid >> 5;
    const int lane  = tid & 31;
    const int kbase = split * K_PER;

    // x[b] into shared (coalesced 2KB)
    s_x[tid] = x[(size_t)b * D_DIM + tid];
    __syncthreads();

    // ---- Phase 1: each warp gathers ROWS_PER_WARP pool rows ----
    int idxs[ROWS_PER_WARP];
#pragma unroll
    for (int r = 0; r < ROWS_PER_WARP; r++) {
        int k = warp * ROWS_PER_WARP + r;
        int v = indices[(size_t)b * K_DIM + kbase + k];
        v = v < 0 ? 0 : (v >= POOL_N ? POOL_N - 1 : v);
        idxs[r] = v;
    }

    // Issue ALL global loads first (8 independent LDG.128 per thread → MLP=8)
    float4 v[ROWS_PER_WARP][4];
#pragma unroll
    for (int r = 0; r < ROWS_PER_WARP; r++) {
        const float4* prow = (const float4*)(pool + (size_t)idxs[r] * D_DIM);
#pragma unroll
        for (int i = 0; i < 4; i++)
            v[r][i] = __ldg(&prow[i * 32 + lane]);
    }

    // Consume: cache to smem + dot against x, then warp-reduce per row
    const float4* sx4 = (const float4*)s_x;
#pragma unroll
    for (int r = 0; r < ROWS_PER_WARP; r++) {
        int k = warp * ROWS_PER_WARP + r;
        float4* srow = (float4*)(s_rows + k * D_DIM);
        float dot = 0.0f;
#pragma unroll
        for (int i = 0; i < 4; i++) {
            int j = i * 32 + lane;
            srow[j] = v[r][i];
            float4 xv = sx4[j];
            dot += v[r][i].x * xv.x + v[r][i].y * xv.y
                 + v[r][i].z * xv.z + v[r][i].w * xv.w;
        }
#pragma unroll
        for (int off = 16; off; off >>= 1)
            dot += __shfl_xor_sync(0xffffffffu, dot, off);
        if (lane == 0)
            s_wact[k] = tanhf(dot) * weights[(size_t)b * K_DIM + kbase + k];
    }
    __syncthreads();

    // ---- Phase 2: partial[d] = sum_k wact[k] * rows[k][d] ----
    float acc = 0.0f;
#pragma unroll 8
    for (int k = 0; k < K_PER; k++)
        acc = fmaf(s_wact[k], s_rows[k * D_DIM + tid], acc);

    if (split == 0)
        out[(size_t)b * D_DIM + tid] = s_x[tid] + acc;   // x + partial0
    else
        g_scratch[(size_t)b * D_DIM + tid] = acc;        // partial1
}

__global__ void __launch_bounds__(1024)
combine_kernel(float* __restrict__ out) {
    size_t i = (size_t)blockIdx.x * 1024 + threadIdx.x;
    out[i] += g_scratch[i];
}

extern "C" void kernel_launch(void* const* d_in, const int* in_sizes, int n_in,
                              void* d_out, int out_size) {
    const float* x       = (const float*)d_in[0];
    const int*   indices = (const int*)d_in[1];
    const float* weights = (const float*)d_in[2];
    const float* pool    = (const float*)d_in[3];
    float*       out     = (float*)d_out;

    cudaFuncSetAttribute(sparse_gather_kernel,
                         cudaFuncAttributeMaxDynamicSharedMemorySize, SMEM_BYTES);

    sparse_gather_kernel<<<B_DIM * SPLIT, THREADS, SMEM_BYTES>>>(
        x, indices, weights, pool, out);

    combine_kernel<<<(B_DIM * D_DIM) / 1024, 1024>>>(out);
}

// round 4
// speedup vs baseline: 1.3018x; 1.1473x over previous
#include <cuda_runtime.h>

#define B_DIM 4096
#define K_DIM 64
#define D_DIM 512
#define POOL_N 1000000
#define THREADS 512
#define SPLIT 2
#define K_PER (K_DIM / SPLIT)          // 32 rows per CTA
#define NWARP (THREADS / 32)           // 16 warps
#define ROWS_PER_WARP (K_PER / NWARP)  // 2 rows per warp

// smem: partials[NWARP][D] | x[D]  = 32KB + 2KB
#define SMEM_FLOATS (NWARP * D_DIM + D_DIM)
#define SMEM_BYTES (SMEM_FLOATS * sizeof(float))

__device__ float g_scratch[(size_t)B_DIM * D_DIM];

__global__ void __launch_bounds__(THREADS, 2)
sparse_gather_kernel(const float* __restrict__ x,
                     const int* __restrict__ indices,
                     const float* __restrict__ weights,
                     const float* __restrict__ pool,
                     float* __restrict__ out) {
    extern __shared__ float smem[];
    float* s_part = smem;                      // NWARP * D
    float* s_x    = smem + NWARP * D_DIM;      // D

    const int b     = blockIdx.x >> 1;
    const int split = blockIdx.x & 1;
    const int tid   = threadIdx.x;
    const int warp  = tid >> 5;
    const int lane  = tid & 31;
    const int kbase = split * K_PER;

    // x[b] into shared (coalesced 2KB)
    s_x[tid] = x[(size_t)b * D_DIM + tid];
    __syncthreads();

    // ---- per-warp: gather 2 rows, dot, tanh*w, accumulate partial ----
    int idxs[ROWS_PER_WARP];
#pragma unroll
    for (int r = 0; r < ROWS_PER_WARP; r++) {
        int k = warp * ROWS_PER_WARP + r;
        int v = indices[(size_t)b * K_DIM + kbase + k];
        v = v < 0 ? 0 : (v >= POOL_N ? POOL_N - 1 : v);
        idxs[r] = v;
    }

    // Issue all 8 global loads up-front (MLP=8 per thread)
    float4 v[ROWS_PER_WARP][4];
#pragma unroll
    for (int r = 0; r < ROWS_PER_WARP; r++) {
        const float4* prow = (const float4*)(pool + (size_t)idxs[r] * D_DIM);
#pragma unroll
        for (int i = 0; i < 4; i++)
            v[r][i] = __ldg(&prow[i * 32 + lane]);
    }

    // x slice this lane needs (same 16 floats for both rows)
    const float4* sx4 = (const float4*)s_x;
    float4 xr[4];
#pragma unroll
    for (int i = 0; i < 4; i++)
        xr[i] = sx4[i * 32 + lane];

    // Dots (both rows), warp-reduce
    float dot[ROWS_PER_WARP];
#pragma unroll
    for (int r = 0; r < ROWS_PER_WARP; r++) {
        float d = 0.0f;
#pragma unroll
        for (int i = 0; i < 4; i++)
            d += v[r][i].x * xr[i].x + v[r][i].y * xr[i].y
               + v[r][i].z * xr[i].z + v[r][i].w * xr[i].w;
#pragma unroll
        for (int off = 16; off; off >>= 1)
            d += __shfl_xor_sync(0xffffffffu, d, off);
        dot[r] = d;   // full value in every lane after butterfly
    }

    // wact for this warp's rows (all lanes: same-address weight load broadcasts)
    float wa[ROWS_PER_WARP];
#pragma unroll
    for (int r = 0; r < ROWS_PER_WARP; r++) {
        int k = warp * ROWS_PER_WARP + r;
        wa[r] = tanhf(dot[r]) * __ldg(&weights[(size_t)b * K_DIM + kbase + k]);
    }

    // Per-warp partial: p[d] = wa0*row0[d] + wa1*row1[d], straight from registers
    float4* pw = (float4*)(s_part + warp * D_DIM);
#pragma unroll
    for (int i = 0; i < 4; i++) {
        float4 p;
        p.x = wa[0] * v[0][i].x + wa[1] * v[1][i].x;
        p.y = wa[0] * v[0][i].y + wa[1] * v[1][i].y;
        p.z = wa[0] * v[0][i].z + wa[1] * v[1][i].z;
        p.w = wa[0] * v[0][i].w + wa[1] * v[1][i].w;
        pw[i * 32 + lane] = p;
    }
    __syncthreads();

    // ---- reduce 16 warp partials (conflict-free: consecutive tid) ----
    float acc = 0.0f;
#pragma unroll
    for (int w = 0; w < NWARP; w++)
        acc += s_part[w * D_DIM + tid];

    if (split == 0)
        out[(size_t)b * D_DIM + tid] = s_x[tid] + acc;
    else
        g_scratch[(size_t)b * D_DIM + tid] = acc;
}

__global__ void __launch_bounds__(256)
combine_kernel(float* __restrict__ out) {
    size_t i = (size_t)blockIdx.x * 256 + threadIdx.x;
    float4* o = (float4*)out;
    const float4* s = (const float4*)g_scratch;
    float4 a = o[i], b = s[i];
    a.x += b.x; a.y += b.y; a.z += b.z; a.w += b.w;
    o[i] = a;
}

extern "C" void kernel_launch(void* const* d_in, const int* in_sizes, int n_in,
                              void* d_out, int out_size) {
    const float* x       = (const float*)d_in[0];
    const int*   indices = (const int*)d_in[1];
    const float* weights = (const float*)d_in[2];
    const float* pool    = (const float*)d_in[3];
    float*       out     = (float*)d_out;

    cudaFuncSetAttribute(sparse_gather_kernel,
                         cudaFuncAttributeMaxDynamicSharedMemorySize, SMEM_BYTES);

    sparse_gather_kernel<<<B_DIM * SPLIT, THREADS, SMEM_BYTES>>>(
        x, indices, weights, pool, out);

    combine_kernel<<<(B_DIM * D_DIM / 4) / 256, 256>>>(out);
}